// round 11
// baseline (speedup 1.0000x reference)
#include <cuda_runtime.h>
#include <cstdint>

#define H 4096
#define NUM_LAYERS 8
#define NBLOCKS 296            // 2 blocks per SM: balance + seam overlap
#define NTHREADS 448           // 14 warps/block
#define WARPS (NTHREADS / 32)

// Row partition: 4096 = 248 blocks * 14 rows + 48 blocks * 13 rows.
#define BASE_ROWS 13
#define EXTRA_BLOCKS 248

// Ping-pong hidden-state buffers (allocation-free scratch).
__device__ float g_h[2][H];

// Software grid-barrier state (monotonic across graph replays).
__device__ unsigned g_bar_count = 0;
__device__ unsigned g_bar_phase = 0;

// Grid-wide barrier. Safe: 296 blocks at 2/SM (enforced by
// __launch_bounds__(448, 2)) are all co-resident on 148 SMs.
__device__ __forceinline__ void grid_barrier() {
    __syncthreads();
    if (threadIdx.x == 0) {
        const unsigned target = *(volatile unsigned*)&g_bar_phase + 1;
        __threadfence();
        const unsigned old = atomicAdd(&g_bar_count, 1);
        if (old == NBLOCKS - 1) {
            *(volatile unsigned*)&g_bar_count = 0;
            __threadfence();
            atomicAdd(&g_bar_phase, 1);
        } else {
            while (*(volatile unsigned*)&g_bar_phase < target)
                __nanosleep(64);
        }
        __threadfence();
    }
    __syncthreads();
}

// One warp computes dot(W[row,:], x_smem): batch-4 LDG.128 schedule
// (4 independent loads in flight; proven best per-warp shape).
__device__ __forceinline__ float row_dot(const float* __restrict__ W,
                                         const float4* __restrict__ sh4,
                                         int row, int lane) {
    const float4* Wr = reinterpret_cast<const float4*>(W + (size_t)row * H);
    float acc[4] = {0.f, 0.f, 0.f, 0.f};
    #pragma unroll
    for (int i = 0; i < 32; i += 4) {
        float4 w[4];
        #pragma unroll
        for (int j = 0; j < 4; j++)
            w[j] = Wr[lane + (i + j) * 32];
        #pragma unroll
        for (int j = 0; j < 4; j++) {
            float4 xv = sh4[lane + (i + j) * 32];
            acc[j] += w[j].x * xv.x + w[j].y * xv.y
                    + w[j].z * xv.z + w[j].w * xv.w;
        }
    }
    float a = (acc[0] + acc[1]) + (acc[2] + acc[3]);
    #pragma unroll
    for (int off = 16; off; off >>= 1)
        a += __shfl_down_sync(0xffffffffu, a, off);
    return a;
}

// Persistent fused RNN (R8 structure). Grid = 296 blocks = 2 per SM:
// keeps R8's seam overlap (one block computes while its SM-sibling spins
// at the grid barrier) AND balances per-SM work (26-28 rows/SM/layer
// instead of R8's 16-vs-32 split).
__global__ void __launch_bounds__(NTHREADS, 2)
rnn_fused_kernel(const float* __restrict__ x,
                 const float* __restrict__ Wxh,
                 const float* __restrict__ bxh,
                 const float* __restrict__ bhh,
                 const float* __restrict__ fc_w,
                 const float* __restrict__ fc_b,
                 float* __restrict__ out) {
    __shared__ float4 sh4[H / 4];   // 16 KB: current input vector

    const int warp = threadIdx.x >> 5;
    const int lane = threadIdx.x & 31;
    const int b    = blockIdx.x;

    // Contiguous row chunk for this block (13 or 14 rows).
    const int extra = (b < EXTRA_BLOCKS) ? b : EXTRA_BLOCKS;
    const int start = b * BASE_ROWS + extra;
    const int cnt   = BASE_ROWS + (b < EXTRA_BLOCKS ? 1 : 0);
    const bool active = (warp < cnt);
    const int row = start + warp;

    const float* cur = x;

    #pragma unroll 1
    for (int l = 0; l < NUM_LAYERS; l++) {
        // Stage the layer input (16 KB) into shared memory.
        const float4* xg = reinterpret_cast<const float4*>(cur);
        for (int i = threadIdx.x; i < H / 4; i += NTHREADS)
            sh4[i] = xg[i];
        __syncthreads();

        if (active) {
            const float a = row_dot(Wxh + (size_t)l * H * H, sh4, row, lane);
            if (lane == 0)
                g_h[l & 1][row] = tanhf(a + bxh[l * H + row] + bhh[l * H + row]);
        }

        grid_barrier();               // publish h before anyone reads it
        cur = g_h[l & 1];
    }

    // Final linear layer (no tanh, single bias) -> d_out.
    {
        const float4* xg = reinterpret_cast<const float4*>(cur);
        for (int i = threadIdx.x; i < H / 4; i += NTHREADS)
            sh4[i] = xg[i];
        __syncthreads();

        if (active) {
            const float a = row_dot(fc_w, sh4, row, lane);
            if (lane == 0)
                out[row] = a + fc_b[row];
        }
    }
}

extern "C" void kernel_launch(void* const* d_in, const int* in_sizes, int n_in,
                              void* d_out, int out_size) {
    const float* x    = (const float*)d_in[0];  // [1, H]
    const float* Wxh  = (const float*)d_in[1];  // [L, H, H]
    const float* bxh  = (const float*)d_in[2];  // [L, H]
    // d_in[3] = Whh — multiplied by a zero vector in the reference; never read.
    const float* bhh  = (const float*)d_in[4];  // [L, H]
    const float* fc_w = (const float*)d_in[5];  // [H, H]
    const float* fc_b = (const float*)d_in[6];  // [H]
    float* out = (float*)d_out;

    rnn_fused_kernel<<<NBLOCKS, NTHREADS>>>(x, Wxh, bxh, bhh, fc_w, fc_b, out);
}

// round 12
// speedup vs baseline: 1.0645x; 1.0645x over previous
#include <cuda_runtime.h>
#include <cstdint>

#define H 4096
#define NUM_LAYERS 8
#define NBLOCKS 256
#define NTHREADS 512          // 16 warps -> 4096 warps == one per row
#define WARPS (NTHREADS / 32)
#define PF 4                  // float4 per lane prefetched across the barrier

// Ping-pong hidden-state buffers (allocation-free scratch).
__device__ float g_h[2][H];

// Software grid-barrier state (monotonic across graph replays).
__device__ unsigned g_bar_count = 0;
__device__ unsigned g_bar_phase = 0;

// Grid-wide barrier. Safe: 256 blocks <= 148 SMs * 2 (enforced by
// __launch_bounds__(512, 2)), all co-resident.
__device__ __forceinline__ void grid_barrier() {
    __syncthreads();
    if (threadIdx.x == 0) {
        const unsigned target = *(volatile unsigned*)&g_bar_phase + 1;
        __threadfence();
        const unsigned old = atomicAdd(&g_bar_count, 1);
        if (old == NBLOCKS - 1) {
            *(volatile unsigned*)&g_bar_count = 0;
            __threadfence();
            atomicAdd(&g_bar_phase, 1);
        } else {
            while (*(volatile unsigned*)&g_bar_phase < target)
                __nanosleep(64);
        }
        __threadfence();
    }
    __syncthreads();
}

// Persistent fused RNN (R8 winner structure) + cross-barrier register
// prefetch: before each grid barrier, every warp issues 4 independent
// LDG.128s for the HEAD (cols 0..511) of its next-layer weight row into
// registers. Weights don't depend on h, so this is always safe, needs no
// synchronization, and keeps DRAM streaming through the barrier-spin /
// x-restage seam that otherwise idles the memory pipe ~1.9us per layer.
__global__ void __launch_bounds__(NTHREADS, 2)
rnn_fused_kernel(const float* __restrict__ x,
                 const float* __restrict__ Wxh,
                 const float* __restrict__ bxh,
                 const float* __restrict__ bhh,
                 const float* __restrict__ fc_w,
                 const float* __restrict__ fc_b,
                 float* __restrict__ out) {
    __shared__ float4 sh4[H / 4];   // 16 KB: current input vector

    const int warp = threadIdx.x >> 5;
    const int lane = threadIdx.x & 31;
    const int row  = blockIdx.x * WARPS + warp;   // 0..4095

    const float* cur = x;

    // Initial prefetch: head of layer 0's row.
    float4 wpre[PF];
    {
        const float4* Wr = reinterpret_cast<const float4*>(Wxh + (size_t)row * H);
        #pragma unroll
        for (int j = 0; j < PF; j++)
            wpre[j] = Wr[lane + j * 32];
    }

    #pragma unroll 1
    for (int l = 0; l <= NUM_LAYERS; l++) {        // 8 tanh layers + fc
        const bool last = (l == NUM_LAYERS);
        const float* Wl = last ? fc_w : Wxh + (size_t)l * H * H;

        // Stage this layer's input (16 KB) into shared memory.
        const float4* xg = reinterpret_cast<const float4*>(cur);
        #pragma unroll
        for (int i = threadIdx.x; i < H / 4; i += NTHREADS)
            sh4[i] = xg[i];
        __syncthreads();

        float acc[4];
        // 1) Consume the prefetched head (cols 0..511) from registers.
        #pragma unroll
        for (int j = 0; j < PF; j++) {
            float4 xv = sh4[lane + j * 32];
            acc[j] = wpre[j].x * xv.x + wpre[j].y * xv.y
                   + wpre[j].z * xv.z + wpre[j].w * xv.w;
        }

        // 2) Stream the rest of the row (cols 512..4095) via batch-4 LDG.128.
        const float4* Wr = reinterpret_cast<const float4*>(Wl + (size_t)row * H);
        #pragma unroll
        for (int i = PF; i < 32; i += 4) {
            float4 w[4];
            #pragma unroll
            for (int j = 0; j < 4; j++)
                w[j] = Wr[lane + (i + j) * 32];
            #pragma unroll
            for (int j = 0; j < 4; j++) {
                float4 xv = sh4[lane + (i + j) * 32];
                acc[j] += w[j].x * xv.x + w[j].y * xv.y
                        + w[j].z * xv.z + w[j].w * xv.w;
            }
        }

        // 3) Issue next layer's head prefetch BEFORE the reduction/barrier so
        //    the loads are in flight while this warp spins at the barrier.
        if (!last) {
            const float* Wn = (l + 1 == NUM_LAYERS) ? fc_w
                                                    : Wxh + (size_t)(l + 1) * H * H;
            const float4* Wrn = reinterpret_cast<const float4*>(Wn + (size_t)row * H);
            #pragma unroll
            for (int j = 0; j < PF; j++)
                wpre[j] = Wrn[lane + j * 32];
        }

        float a = (acc[0] + acc[1]) + (acc[2] + acc[3]);
        #pragma unroll
        for (int off = 16; off; off >>= 1)
            a += __shfl_down_sync(0xffffffffu, a, off);

        if (last) {
            if (lane == 0)
                out[row] = a + fc_b[row];
        } else {
            if (lane == 0)
                g_h[l & 1][row] = tanhf(a + bxh[l * H + row] + bhh[l * H + row]);
            grid_barrier();           // publish h before anyone reads it
            cur = g_h[l & 1];
        }
    }
}

extern "C" void kernel_launch(void* const* d_in, const int* in_sizes, int n_in,
                              void* d_out, int out_size) {
    const float* x    = (const float*)d_in[0];  // [1, H]
    const float* Wxh  = (const float*)d_in[1];  // [L, H, H]
    const float* bxh  = (const float*)d_in[2];  // [L, H]
    // d_in[3] = Whh — multiplied by a zero vector in the reference; never read.
    const float* bhh  = (const float*)d_in[4];  // [L, H]
    const float* fc_w = (const float*)d_in[5];  // [H, H]
    const float* fc_b = (const float*)d_in[6];  // [H]
    float* out = (float*)d_out;

    rnn_fused_kernel<<<NBLOCKS, NTHREADS>>>(x, Wxh, bxh, bhh, fc_w, fc_b, out);
}